// round 10
// baseline (speedup 1.0000x reference)
#include <cuda_runtime.h>

// ---------------- problem constants ----------------
#define B_ 16
#define N_ 512
#define H_ 512
#define G_ 8
#define L_ 16
#define D_ 64
#define SCALE_ 0.04419417382415922f   // 512^-0.5

// ---------------- device scratch (static: no allocs allowed) ----------------
__device__ float g_Q[B_*G_*N_*D_];          // (b,g,n,d)  16 MB
__device__ float g_K[B_*G_*N_*D_];          // (b,g,m,d)  16 MB
__device__ float g_V[B_*L_*N_*D_];          // (b,l,m,d)  32 MB
__device__ float g_S[B_*G_*N_*N_];          // (b,g,n,m) 128 MB
__device__ float g_A[B_*L_*N_*N_];          // (b,l,n,m) 256 MB
__device__ float g_O[B_*N_*L_*D_];          // (b,n,l,d)  32 MB

// ---------------- f32x2 helpers (FFMA2 only reachable via PTX) --------------
__device__ __forceinline__ unsigned long long pk2(float v) {
    unsigned long long r;
    asm("mov.b64 %0, {%1, %1};" : "=l"(r) : "f"(v));
    return r;
}
__device__ __forceinline__ void ffma2(unsigned long long& d,
                                      unsigned long long a,
                                      unsigned long long b) {
    asm("fma.rn.f32x2 %0, %1, %2, %0;" : "+l"(d) : "l"(a), "l"(b));
}
__device__ __forceinline__ float2 up2(unsigned long long v) {
    float2 f;
    asm("mov.b64 {%0, %1}, %2;" : "=f"(f.x), "=f"(f.y) : "l"(v));
    return f;
}

// mish(x) = x * tanh(softplus(x)) = x * (t^2+2t)/(t^2+2t+2), t = e^x
__device__ __forceinline__ float mishf(float x) {
    float t = __expf(fminf(x, 15.f));   // clamp: for x>15 ratio == 1 to fp32
    float u = t * t + 2.f * t;
    return x * __fdividef(u, u + 2.f);
}

// =============================================================================
// K1: QKV projection.  C(8192 x 2048) = X(8192x512) @ [Wq|Wk|Wv], scatter into
// g_Q (b,g,n,d), g_K (b,g,m,d), g_V (b,l,m,d) (+bv).
// Tile 128x128x16, 256 thr, 8x8/thread, f32x2 accumulators over row pairs.
// =============================================================================
__global__ void __launch_bounds__(256)
k1_proj(const float* __restrict__ x,  const float* __restrict__ Wq,
        const float* __restrict__ Wk, const float* __restrict__ Wv,
        const float* __restrict__ bv)
{
    __shared__ __align__(16) float As[16][130];  // transposed, pad 130 -> conflict-free
    __shared__ __align__(16) float Bs[16][128];

    const int tid = threadIdx.x;
    const int colTile = blockIdx.x;   // 0..15 (16 * 128 = 2048 cols)
    const int rowTile = blockIdx.y;   // 0..63

    const float* Wsrc; int colBase, mode, ldw;
    if (colTile < 4)      { Wsrc = Wq; colBase = colTile * 128;       mode = 0; ldw = 512;  }
    else if (colTile < 8) { Wsrc = Wk; colBase = (colTile - 4) * 128; mode = 1; ldw = 512;  }
    else                  { Wsrc = Wv; colBase = (colTile - 8) * 128; mode = 2; ldw = 1024; }

    const float* Ag = x + (size_t)rowTile * 128 * 512;

    const int ti = tid >> 4, tj = tid & 15;
    const int i0 = ti * 8, j0 = tj * 8;
    const int akk = tid & 15, arb = tid >> 4;

    unsigned long long c2[4][8];
#pragma unroll
    for (int p = 0; p < 4; p++)
#pragma unroll
        for (int j = 0; j < 8; j++) c2[p][j] = 0ull;

    for (int k0 = 0; k0 < 512; k0 += 16) {
#pragma unroll
        for (int it = 0; it < 8; it++) {
            int r = arb + 16 * it;
            As[akk][r] = Ag[(size_t)r * 512 + k0 + akk];
        }
#pragma unroll
        for (int it = 0; it < 2; it++) {
            int li = tid + 256 * it;
            int bkk = li >> 5, bjc = li & 31;
            *(float4*)&Bs[bkk][bjc * 4] =
                *(const float4*)&Wsrc[(size_t)(k0 + bkk) * ldw + colBase + bjc * 4];
        }
        __syncthreads();
#pragma unroll
        for (int kk = 0; kk < 16; kk++) {
            unsigned long long a2[4];
#pragma unroll
            for (int p = 0; p < 4; p++)
                a2[p] = *(const unsigned long long*)&As[kk][i0 + 2 * p];
            float4 b0 = *(const float4*)&Bs[kk][j0];
            float4 b1 = *(const float4*)&Bs[kk][j0 + 4];
            unsigned long long bb[8] = { pk2(b0.x), pk2(b0.y), pk2(b0.z), pk2(b0.w),
                                         pk2(b1.x), pk2(b1.y), pk2(b1.z), pk2(b1.w) };
#pragma unroll
            for (int p = 0; p < 4; p++)
#pragma unroll
                for (int j = 0; j < 8; j++) ffma2(c2[p][j], a2[p], bb[j]);
        }
        __syncthreads();
    }

    const int c = colBase + j0;            // 8 consecutive cols, same head (c%64 multiple of 8)
#pragma unroll
    for (int p = 0; p < 4; p++) {
        float2 rows[8];
#pragma unroll
        for (int j = 0; j < 8; j++) rows[j] = up2(c2[p][j]);
#pragma unroll
        for (int h = 0; h < 2; h++) {
            int i = i0 + 2 * p + h;
            int r = rowTile * 128 + i;
            int b = r >> 9, n = r & 511;
            float v[8];
#pragma unroll
            for (int j = 0; j < 8; j++) v[j] = h ? rows[j].y : rows[j].x;
            if (mode == 2) {
#pragma unroll
                for (int j = 0; j < 8; j++) v[j] += bv[c + j];
                int l = c >> 6, d = c & 63;
                float* dst = &g_V[(((b * 16 + l) * 512 + n) * 64) + d];
                *(float4*)dst       = make_float4(v[0], v[1], v[2], v[3]);
                *(float4*)(dst + 4) = make_float4(v[4], v[5], v[6], v[7]);
            } else {
                int g = c >> 6, d = c & 63;
                float* base = (mode == 0) ? g_Q : g_K;
                float* dst = base + (((b * 8 + g) * 512 + n) * 64) + d;
                *(float4*)dst       = make_float4(v[0], v[1], v[2], v[3]);
                *(float4*)(dst + 4) = make_float4(v[4], v[5], v[6], v[7]);
            }
        }
    }
}

// =============================================================================
// K2: scores. For each z=(b,g): S_z(512x512) = Q_z(512x64) @ K_z(512x64)^T.
// NT GEMM: both operands transpose-loaded into smem (pad 130).
// =============================================================================
__global__ void __launch_bounds__(256)
k2_scores()
{
    __shared__ __align__(16) float As[16][130];
    __shared__ __align__(16) float Bs[16][130];

    const int tid = threadIdx.x;
    const int z = blockIdx.z;                         // b*8+g
    const float* Qg = g_Q + (size_t)z * 512 * 64;
    const float* Kg = g_K + (size_t)z * 512 * 64;
    const int rowTile = blockIdx.y, colTile = blockIdx.x;   // each 0..3

    const int ti = tid >> 4, tj = tid & 15;
    const int i0 = ti * 8, j0 = tj * 8;
    const int lkk = tid & 15, lrb = tid >> 4;

    unsigned long long c2[4][8];
#pragma unroll
    for (int p = 0; p < 4; p++)
#pragma unroll
        for (int j = 0; j < 8; j++) c2[p][j] = 0ull;

    for (int k0 = 0; k0 < 64; k0 += 16) {
#pragma unroll
        for (int it = 0; it < 8; it++) {
            int r = lrb + 16 * it;
            As[lkk][r] = Qg[(size_t)(rowTile * 128 + r) * 64 + k0 + lkk];
            Bs[lkk][r] = Kg[(size_t)(colTile * 128 + r) * 64 + k0 + lkk];
        }
        __syncthreads();
#pragma unroll
        for (int kk = 0; kk < 16; kk++) {
            unsigned long long a2[4];
#pragma unroll
            for (int p = 0; p < 4; p++)
                a2[p] = *(const unsigned long long*)&As[kk][i0 + 2 * p];
            unsigned long long bb[8];
#pragma unroll
            for (int q = 0; q < 4; q++) {
                float2 bq = *(const float2*)&Bs[kk][j0 + 2 * q];
                bb[2 * q]     = pk2(bq.x);
                bb[2 * q + 1] = pk2(bq.y);
            }
#pragma unroll
            for (int p = 0; p < 4; p++)
#pragma unroll
                for (int j = 0; j < 8; j++) ffma2(c2[p][j], a2[p], bb[j]);
        }
        __syncthreads();
    }

    float* Sb = g_S + (size_t)z * 512 * 512;
#pragma unroll
    for (int p = 0; p < 4; p++) {
        float2 rows[8];
#pragma unroll
        for (int j = 0; j < 8; j++) rows[j] = up2(c2[p][j]);
#pragma unroll
        for (int h = 0; h < 2; h++) {
            int n = rowTile * 128 + i0 + 2 * p + h;
            float v[8];
#pragma unroll
            for (int j = 0; j < 8; j++) v[j] = h ? rows[j].y : rows[j].x;
            float* dst = Sb + (size_t)n * 512 + colTile * 128 + j0;
            *(float4*)dst       = make_float4(v[0], v[1], v[2], v[3]);
            *(float4*)(dst + 4) = make_float4(v[4], v[5], v[6], v[7]);
        }
    }
}

// =============================================================================
// K3: pointwise head-mix. a8 = S + sigma^2*eps; a16 = mish(a8@Wp1+bp1)@Wp2+bp2;
// a16 = a16*SCALE + prior(b,l,n,m); softmax over l (16); write A (b,l,n,m).
// 2 points per thread (m and m+256) to amortize weight LDS.
// =============================================================================
__global__ void __launch_bounds__(256)
k3_mix(const float* __restrict__ eps,  const float* __restrict__ prior,
       const float* __restrict__ sigma, const float* __restrict__ Wp1,
       const float* __restrict__ bp1,   const float* __restrict__ Wp2,
       const float* __restrict__ bp2)
{
    __shared__ float W1s[128];
    __shared__ float W2s[256];
    __shared__ float b1s[16], b2s[16], sg2[8];

    const int tid = threadIdx.x;
    if (tid < 128) W1s[tid] = Wp1[tid];
    W2s[tid] = Wp2[tid];
    if (tid < 16) { b1s[tid] = bp1[tid]; b2s[tid] = bp2[tid]; }
    if (tid < 8)  { float s = sigma[tid]; sg2[tid] = s * s; }
    __syncthreads();

    const int gidx = blockIdx.x * 256 + tid;   // grid 8192 -> 2.097M threads
    const int m = gidx & 255;
    const int n = (gidx >> 8) & 511;
    const int b = gidx >> 17;

    const size_t p0 = ((size_t)(b * 512 + n)) * 512 + m;   // (b,n,m) flat

    float t0[8], t1[8];
    {
        float e0[8], e1[8];
        const float4* ep0 = (const float4*)(eps + p0 * 8);
        const float4* ep1 = (const float4*)(eps + (p0 + 256) * 8);
        *(float4*)&e0[0] = ep0[0]; *(float4*)&e0[4] = ep0[1];
        *(float4*)&e1[0] = ep1[0]; *(float4*)&e1[4] = ep1[1];
#pragma unroll
        for (int g = 0; g < 8; g++) {
            size_t si = ((size_t)(b * 8 + g) * 512 + n) * 512 + m;
            t0[g] = g_S[si]       + sg2[g] * e0[g];
            t1[g] = g_S[si + 256] + sg2[g] * e1[g];
        }
    }

    float h0[16], h1[16];
#pragma unroll
    for (int l = 0; l < 16; l++) {
        float a0 = b1s[l], a1 = b1s[l];
#pragma unroll
        for (int g = 0; g < 8; g++) {
            float w = W1s[g * 16 + l];
            a0 += t0[g] * w; a1 += t1[g] * w;
        }
        h0[l] = mishf(a0); h1[l] = mishf(a1);
    }

    float a0[16], a1[16];
    const size_t pr = ((size_t)(b * 16) * 512 + n) * 512 + m;   // l stride = 512*512
    float mx0 = -1e30f, mx1 = -1e30f;
#pragma unroll
    for (int l = 0; l < 16; l++) {
        float s0 = b2s[l], s1 = b2s[l];
#pragma unroll
        for (int j = 0; j < 16; j++) {
            float w = W2s[j * 16 + l];
            s0 += h0[j] * w; s1 += h1[j] * w;
        }
        size_t pl = pr + (size_t)l * (512 * 512);
        s0 = s0 * SCALE_ + prior[pl];
        s1 = s1 * SCALE_ + prior[pl + 256];
        a0[l] = s0; a1[l] = s1;
        mx0 = fmaxf(mx0, s0); mx1 = fmaxf(mx1, s1);
    }

    float sum0 = 0.f, sum1 = 0.f;
#pragma unroll
    for (int l = 0; l < 16; l++) {
        a0[l] = __expf(a0[l] - mx0); sum0 += a0[l];
        a1[l] = __expf(a1[l] - mx1); sum1 += a1[l];
    }
    float r0 = __fdividef(1.f, sum0), r1 = __fdividef(1.f, sum1);
#pragma unroll
    for (int l = 0; l < 16; l++) {
        size_t pl = pr + (size_t)l * (512 * 512);
        g_A[pl]       = a0[l] * r0;
        g_A[pl + 256] = a1[l] * r1;
    }
}

// =============================================================================
// K4: AV. For each batch=(b,l): O(512x64) = A_l(512x512) @ V_l(512x64).
// Tile 128x64x16, 256 thr, 8x4/thread.
// =============================================================================
__global__ void __launch_bounds__(256)
k4_av()
{
    __shared__ __align__(16) float As[16][130];
    __shared__ __align__(16) float Bs[16][64];

    const int tid = threadIdx.x;
    const int batch = blockIdx.y;       // 0..255 = b*16+l
    const int rowTile = blockIdx.x;     // 0..3
    const float* Aa = g_A + (size_t)batch * 512 * 512 + (size_t)rowTile * 128 * 512;
    const float* Vv = g_V + (size_t)batch * 512 * 64;

    const int ti = tid >> 4, tj = tid & 15;
    const int i0 = ti * 8, j0 = tj * 4;
    const int akk = tid & 15, arb = tid >> 4;
    const int bkk = tid >> 4, bjc = tid & 15;

    unsigned long long c2[4][4];
#pragma unroll
    for (int p = 0; p < 4; p++)
#pragma unroll
        for (int j = 0; j < 4; j++) c2[p][j] = 0ull;

    for (int k0 = 0; k0 < 512; k0 += 16) {
#pragma unroll
        for (int it = 0; it < 8; it++) {
            int r = arb + 16 * it;
            As[akk][r] = Aa[(size_t)r * 512 + k0 + akk];
        }
        *(float4*)&Bs[bkk][bjc * 4] = *(const float4*)&Vv[(size_t)(k0 + bkk) * 64 + bjc * 4];
        __syncthreads();
#pragma unroll
        for (int kk = 0; kk < 16; kk++) {
            unsigned long long a2[4];
#pragma unroll
            for (int p = 0; p < 4; p++)
                a2[p] = *(const unsigned long long*)&As[kk][i0 + 2 * p];
            float4 bq = *(const float4*)&Bs[kk][j0];
            unsigned long long bb[4] = { pk2(bq.x), pk2(bq.y), pk2(bq.z), pk2(bq.w) };
#pragma unroll
            for (int p = 0; p < 4; p++)
#pragma unroll
                for (int j = 0; j < 4; j++) ffma2(c2[p][j], a2[p], bb[j]);
        }
        __syncthreads();
    }

    const int b = batch >> 4, l = batch & 15;
#pragma unroll
    for (int p = 0; p < 4; p++) {
        float2 rows[4];
#pragma unroll
        for (int j = 0; j < 4; j++) rows[j] = up2(c2[p][j]);
#pragma unroll
        for (int h = 0; h < 2; h++) {
            int n = rowTile * 128 + i0 + 2 * p + h;
            float v[4];
#pragma unroll
            for (int j = 0; j < 4; j++) v[j] = h ? rows[j].y : rows[j].x;
            float* dst = &g_O[(((b * 512 + n) * 16 + l) * 64) + j0];
            *(float4*)dst = make_float4(v[0], v[1], v[2], v[3]);
        }
    }
}

// =============================================================================
// K5: output projection. out(8192x512) = O(8192x1024) @ Wout(1024x512).
// =============================================================================
__global__ void __launch_bounds__(256)
k5_out(const float* __restrict__ Wout, float* __restrict__ out)
{
    __shared__ __align__(16) float As[16][130];
    __shared__ __align__(16) float Bs[16][128];

    const int tid = threadIdx.x;
    const int colTile = blockIdx.x;   // 0..3
    const int rowTile = blockIdx.y;   // 0..63
    const float* Ag = g_O + (size_t)rowTile * 128 * 1024;
    const int colBase = colTile * 128;

    const int ti = tid >> 4, tj = tid & 15;
    const int i0 = ti * 8, j0 = tj * 8;
    const int akk = tid & 15, arb = tid >> 4;

    unsigned long long c2[4][8];
#pragma unroll
    for (int p = 0; p < 4; p++)
#pragma unroll
        for (int j = 0; j < 8; j++) c2[p][j] = 0ull;

    for (int k0 = 0; k0 < 1024; k0 += 16) {
#pragma unroll
        for (int it = 0; it < 8; it++) {
            int r = arb + 16 * it;
            As[akk][r] = Ag[(size_t)r * 1024 + k0 + akk];
        }
#pragma unroll
        for (int it = 0; it < 2; it++) {
            int li = tid + 256 * it;
            int bkk = li >> 5, bjc = li & 31;
            *(float4*)&Bs[bkk][bjc * 4] =
                *(const float4*)&Wout[(size_t)(k0 + bkk) * 512 + colBase + bjc * 4];
        }
        __syncthreads();
#pragma unroll
        for (int kk = 0; kk < 16; kk++) {
            unsigned long long a2[4];
#pragma unroll
            for (int p = 0; p < 4; p++)
                a2[p] = *(const unsigned long long*)&As[kk][i0 + 2 * p];
            float4 b0 = *(const float4*)&Bs[kk][j0];
            float4 b1 = *(const float4*)&Bs[kk][j0 + 4];
            unsigned long long bb[8] = { pk2(b0.x), pk2(b0.y), pk2(b0.z), pk2(b0.w),
                                         pk2(b1.x), pk2(b1.y), pk2(b1.z), pk2(b1.w) };
#pragma unroll
            for (int p = 0; p < 4; p++)
#pragma unroll
                for (int j = 0; j < 8; j++) ffma2(c2[p][j], a2[p], bb[j]);
        }
        __syncthreads();
    }

#pragma unroll
    for (int p = 0; p < 4; p++) {
        float2 rows[8];
#pragma unroll
        for (int j = 0; j < 8; j++) rows[j] = up2(c2[p][j]);
#pragma unroll
        for (int h = 0; h < 2; h++) {
            int r = rowTile * 128 + i0 + 2 * p + h;
            float v[8];
#pragma unroll
            for (int j = 0; j < 8; j++) v[j] = h ? rows[j].y : rows[j].x;
            float* dst = out + (size_t)r * 512 + colBase + j0;
            *(float4*)dst       = make_float4(v[0], v[1], v[2], v[3]);
            *(float4*)(dst + 4) = make_float4(v[4], v[5], v[6], v[7]);
        }
    }
}

// =============================================================================
extern "C" void kernel_launch(void* const* d_in, const int* in_sizes, int n_in,
                              void* d_out, int out_size)
{
    (void)in_sizes; (void)n_in; (void)out_size;
    const float* x     = (const float*)d_in[0];
    const float* prior = (const float*)d_in[1];
    const float* eps   = (const float*)d_in[2];
    const float* Wq    = (const float*)d_in[3];
    const float* Wk    = (const float*)d_in[4];
    const float* Wv    = (const float*)d_in[5];
    const float* bv    = (const float*)d_in[6];
    const float* sigma = (const float*)d_in[7];
    const float* Wp1   = (const float*)d_in[8];
    const float* bp1   = (const float*)d_in[9];
    const float* Wp2   = (const float*)d_in[10];
    const float* bp2   = (const float*)d_in[11];
    const float* Wout  = (const float*)d_in[12];
    float* out = (float*)d_out;

    k1_proj  <<<dim3(16, 64),     256>>>(x, Wq, Wk, Wv, bv);
    k2_scores<<<dim3(4, 4, 128),  256>>>();
    k3_mix   <<<8192,             256>>>(eps, prior, sigma, Wp1, bp1, Wp2, bp2);
    k4_av    <<<dim3(4, 256),     256>>>();
    k5_out   <<<dim3(4, 64),      256>>>(Wout, out);
}

// round 11
// speedup vs baseline: 1.0002x; 1.0002x over previous
#include <cuda_runtime.h>

// ---------------- problem constants ----------------
#define B_ 16
#define N_ 512
#define H_ 512
#define G_ 8
#define L_ 16
#define D_ 64
#define SCALE_ 0.04419417382415922f   // 512^-0.5

// ---------------- device scratch (static: no allocs allowed) ----------------
__device__ float g_Q[B_*G_*N_*D_];          // (b,g,n,d)  16 MB
__device__ float g_K[B_*G_*N_*D_];          // (b,g,m,d)  16 MB
__device__ float g_V[B_*L_*N_*D_];          // (b,l,m,d)  32 MB
__device__ float g_S[B_*G_*N_*N_];          // (b,g,n,m) 128 MB
__device__ float g_A[B_*L_*N_*N_];          // (b,l,n,m) 256 MB
__device__ float g_O[B_*N_*L_*D_];          // (b,n,l,d)  32 MB

// ---------------- f32x2 helpers (FFMA2 only reachable via PTX) --------------
__device__ __forceinline__ unsigned long long pk2(float v) {
    unsigned long long r;
    asm("mov.b64 %0, {%1, %1};" : "=l"(r) : "f"(v));
    return r;
}
__device__ __forceinline__ void ffma2(unsigned long long& d,
                                      unsigned long long a,
                                      unsigned long long b) {
    asm("fma.rn.f32x2 %0, %1, %2, %0;" : "+l"(d) : "l"(a), "l"(b));
}
__device__ __forceinline__ float2 up2(unsigned long long v) {
    float2 f;
    asm("mov.b64 {%0, %1}, %2;" : "=f"(f.x), "=f"(f.y) : "l"(v));
    return f;
}

// mish(x) = x * tanh(softplus(x)) = x * (t^2+2t)/(t^2+2t+2), t = e^x
__device__ __forceinline__ float mishf(float x) {
    float t = __expf(fminf(x, 15.f));   // clamp: for x>15 ratio == 1 to fp32
    float u = t * t + 2.f * t;
    return x * __fdividef(u, u + 2.f);
}

// =============================================================================
// K1: QKV projection.  C(8192 x 2048) = X(8192x512) @ [Wq|Wk|Wv], scatter into
// g_Q (b,g,n,d), g_K (b,g,m,d), g_V (b,l,m,d) (+bv).
// Tile 128x128x16, 256 thr, 8x8/thread, f32x2 accumulators over row pairs.
// =============================================================================
__global__ void __launch_bounds__(256)
k1_proj(const float* __restrict__ x,  const float* __restrict__ Wq,
        const float* __restrict__ Wk, const float* __restrict__ Wv,
        const float* __restrict__ bv)
{
    __shared__ __align__(16) float As[16][130];  // transposed, pad 130 -> conflict-free
    __shared__ __align__(16) float Bs[16][128];

    const int tid = threadIdx.x;
    const int colTile = blockIdx.x;   // 0..15 (16 * 128 = 2048 cols)
    const int rowTile = blockIdx.y;   // 0..63

    const float* Wsrc; int colBase, mode, ldw;
    if (colTile < 4)      { Wsrc = Wq; colBase = colTile * 128;       mode = 0; ldw = 512;  }
    else if (colTile < 8) { Wsrc = Wk; colBase = (colTile - 4) * 128; mode = 1; ldw = 512;  }
    else                  { Wsrc = Wv; colBase = (colTile - 8) * 128; mode = 2; ldw = 1024; }

    const float* Ag = x + (size_t)rowTile * 128 * 512;

    const int ti = tid >> 4, tj = tid & 15;
    const int i0 = ti * 8, j0 = tj * 8;
    const int akk = tid & 15, arb = tid >> 4;

    unsigned long long c2[4][8];
#pragma unroll
    for (int p = 0; p < 4; p++)
#pragma unroll
        for (int j = 0; j < 8; j++) c2[p][j] = 0ull;

    for (int k0 = 0; k0 < 512; k0 += 16) {
#pragma unroll
        for (int it = 0; it < 8; it++) {
            int r = arb + 16 * it;
            As[akk][r] = Ag[(size_t)r * 512 + k0 + akk];
        }
#pragma unroll
        for (int it = 0; it < 2; it++) {
            int li = tid + 256 * it;
            int bkk = li >> 5, bjc = li & 31;
            *(float4*)&Bs[bkk][bjc * 4] =
                *(const float4*)&Wsrc[(size_t)(k0 + bkk) * ldw + colBase + bjc * 4];
        }
        __syncthreads();
#pragma unroll
        for (int kk = 0; kk < 16; kk++) {
            unsigned long long a2[4];
#pragma unroll
            for (int p = 0; p < 4; p++)
                a2[p] = *(const unsigned long long*)&As[kk][i0 + 2 * p];
            float4 b0 = *(const float4*)&Bs[kk][j0];
            float4 b1 = *(const float4*)&Bs[kk][j0 + 4];
            unsigned long long bb[8] = { pk2(b0.x), pk2(b0.y), pk2(b0.z), pk2(b0.w),
                                         pk2(b1.x), pk2(b1.y), pk2(b1.z), pk2(b1.w) };
#pragma unroll
            for (int p = 0; p < 4; p++)
#pragma unroll
                for (int j = 0; j < 8; j++) ffma2(c2[p][j], a2[p], bb[j]);
        }
        __syncthreads();
    }

    const int c = colBase + j0;            // 8 consecutive cols, same head (c%64 multiple of 8)
#pragma unroll
    for (int p = 0; p < 4; p++) {
        float2 rows[8];
#pragma unroll
        for (int j = 0; j < 8; j++) rows[j] = up2(c2[p][j]);
#pragma unroll
        for (int h = 0; h < 2; h++) {
            int i = i0 + 2 * p + h;
            int r = rowTile * 128 + i;
            int b = r >> 9, n = r & 511;
            float v[8];
#pragma unroll
            for (int j = 0; j < 8; j++) v[j] = h ? rows[j].y : rows[j].x;
            if (mode == 2) {
#pragma unroll
                for (int j = 0; j < 8; j++) v[j] += bv[c + j];
                int l = c >> 6, d = c & 63;
                float* dst = &g_V[(((b * 16 + l) * 512 + n) * 64) + d];
                *(float4*)dst       = make_float4(v[0], v[1], v[2], v[3]);
                *(float4*)(dst + 4) = make_float4(v[4], v[5], v[6], v[7]);
            } else {
                int g = c >> 6, d = c & 63;
                float* base = (mode == 0) ? g_Q : g_K;
                float* dst = base + (((b * 8 + g) * 512 + n) * 64) + d;
                *(float4*)dst       = make_float4(v[0], v[1], v[2], v[3]);
                *(float4*)(dst + 4) = make_float4(v[4], v[5], v[6], v[7]);
            }
        }
    }
}

// =============================================================================
// K2: scores. For each z=(b,g): S_z(512x512) = Q_z(512x64) @ K_z(512x64)^T.
// NT GEMM: both operands transpose-loaded into smem (pad 130).
// =============================================================================
__global__ void __launch_bounds__(256)
k2_scores()
{
    __shared__ __align__(16) float As[16][130];
    __shared__ __align__(16) float Bs[16][130];

    const int tid = threadIdx.x;
    const int z = blockIdx.z;                         // b*8+g
    const float* Qg = g_Q + (size_t)z * 512 * 64;
    const float* Kg = g_K + (size_t)z * 512 * 64;
    const int rowTile = blockIdx.y, colTile = blockIdx.x;   // each 0..3

    const int ti = tid >> 4, tj = tid & 15;
    const int i0 = ti * 8, j0 = tj * 8;
    const int lkk = tid & 15, lrb = tid >> 4;

    unsigned long long c2[4][8];
#pragma unroll
    for (int p = 0; p < 4; p++)
#pragma unroll
        for (int j = 0; j < 8; j++) c2[p][j] = 0ull;

    for (int k0 = 0; k0 < 64; k0 += 16) {
#pragma unroll
        for (int it = 0; it < 8; it++) {
            int r = lrb + 16 * it;
            As[lkk][r] = Qg[(size_t)(rowTile * 128 + r) * 64 + k0 + lkk];
            Bs[lkk][r] = Kg[(size_t)(colTile * 128 + r) * 64 + k0 + lkk];
        }
        __syncthreads();
#pragma unroll
        for (int kk = 0; kk < 16; kk++) {
            unsigned long long a2[4];
#pragma unroll
            for (int p = 0; p < 4; p++)
                a2[p] = *(const unsigned long long*)&As[kk][i0 + 2 * p];
            unsigned long long bb[8];
#pragma unroll
            for (int q = 0; q < 4; q++) {
                float2 bq = *(const float2*)&Bs[kk][j0 + 2 * q];
                bb[2 * q]     = pk2(bq.x);
                bb[2 * q + 1] = pk2(bq.y);
            }
#pragma unroll
            for (int p = 0; p < 4; p++)
#pragma unroll
                for (int j = 0; j < 8; j++) ffma2(c2[p][j], a2[p], bb[j]);
        }
        __syncthreads();
    }

    float* Sb = g_S + (size_t)z * 512 * 512;
#pragma unroll
    for (int p = 0; p < 4; p++) {
        float2 rows[8];
#pragma unroll
        for (int j = 0; j < 8; j++) rows[j] = up2(c2[p][j]);
#pragma unroll
        for (int h = 0; h < 2; h++) {
            int n = rowTile * 128 + i0 + 2 * p + h;
            float v[8];
#pragma unroll
            for (int j = 0; j < 8; j++) v[j] = h ? rows[j].y : rows[j].x;
            float* dst = Sb + (size_t)n * 512 + colTile * 128 + j0;
            *(float4*)dst       = make_float4(v[0], v[1], v[2], v[3]);
            *(float4*)(dst + 4) = make_float4(v[4], v[5], v[6], v[7]);
        }
    }
}

// =============================================================================
// K3: pointwise head-mix. a8 = S + sigma^2*eps; a16 = mish(a8@Wp1+bp1)@Wp2+bp2;
// a16 = a16*SCALE + prior(b,l,n,m); softmax over l (16); write A (b,l,n,m).
// 2 points per thread (m and m+256) to amortize weight LDS.
// =============================================================================
__global__ void __launch_bounds__(256)
k3_mix(const float* __restrict__ eps,  const float* __restrict__ prior,
       const float* __restrict__ sigma, const float* __restrict__ Wp1,
       const float* __restrict__ bp1,   const float* __restrict__ Wp2,
       const float* __restrict__ bp2)
{
    __shared__ float W1s[128];
    __shared__ float W2s[256];
    __shared__ float b1s[16], b2s[16], sg2[8];

    const int tid = threadIdx.x;
    if (tid < 128) W1s[tid] = Wp1[tid];
    W2s[tid] = Wp2[tid];
    if (tid < 16) { b1s[tid] = bp1[tid]; b2s[tid] = bp2[tid]; }
    if (tid < 8)  { float s = sigma[tid]; sg2[tid] = s * s; }
    __syncthreads();

    const int gidx = blockIdx.x * 256 + tid;   // grid 8192 -> 2.097M threads
    const int m = gidx & 255;
    const int n = (gidx >> 8) & 511;
    const int b = gidx >> 17;

    const size_t p0 = ((size_t)(b * 512 + n)) * 512 + m;   // (b,n,m) flat

    float t0[8], t1[8];
    {
        float e0[8], e1[8];
        const float4* ep0 = (const float4*)(eps + p0 * 8);
        const float4* ep1 = (const float4*)(eps + (p0 + 256) * 8);
        *(float4*)&e0[0] = ep0[0]; *(float4*)&e0[4] = ep0[1];
        *(float4*)&e1[0] = ep1[0]; *(float4*)&e1[4] = ep1[1];
#pragma unroll
        for (int g = 0; g < 8; g++) {
            size_t si = ((size_t)(b * 8 + g) * 512 + n) * 512 + m;
            t0[g] = g_S[si]       + sg2[g] * e0[g];
            t1[g] = g_S[si + 256] + sg2[g] * e1[g];
        }
    }

    float h0[16], h1[16];
#pragma unroll
    for (int l = 0; l < 16; l++) {
        float a0 = b1s[l], a1 = b1s[l];
#pragma unroll
        for (int g = 0; g < 8; g++) {
            float w = W1s[g * 16 + l];
            a0 += t0[g] * w; a1 += t1[g] * w;
        }
        h0[l] = mishf(a0); h1[l] = mishf(a1);
    }

    float a0[16], a1[16];
    const size_t pr = ((size_t)(b * 16) * 512 + n) * 512 + m;   // l stride = 512*512
    float mx0 = -1e30f, mx1 = -1e30f;
#pragma unroll
    for (int l = 0; l < 16; l++) {
        float s0 = b2s[l], s1 = b2s[l];
#pragma unroll
        for (int j = 0; j < 16; j++) {
            float w = W2s[j * 16 + l];
            s0 += h0[j] * w; s1 += h1[j] * w;
        }
        size_t pl = pr + (size_t)l * (512 * 512);
        s0 = s0 * SCALE_ + prior[pl];
        s1 = s1 * SCALE_ + prior[pl + 256];
        a0[l] = s0; a1[l] = s1;
        mx0 = fmaxf(mx0, s0); mx1 = fmaxf(mx1, s1);
    }

    float sum0 = 0.f, sum1 = 0.f;
#pragma unroll
    for (int l = 0; l < 16; l++) {
        a0[l] = __expf(a0[l] - mx0); sum0 += a0[l];
        a1[l] = __expf(a1[l] - mx1); sum1 += a1[l];
    }
    float r0 = __fdividef(1.f, sum0), r1 = __fdividef(1.f, sum1);
#pragma unroll
    for (int l = 0; l < 16; l++) {
        size_t pl = pr + (size_t)l * (512 * 512);
        g_A[pl]       = a0[l] * r0;
        g_A[pl + 256] = a1[l] * r1;
    }
}

// =============================================================================
// K4: AV. For each batch=(b,l): O(512x64) = A_l(512x512) @ V_l(512x64).
// Tile 128x64x16, 256 thr, 8x4/thread.
// =============================================================================
__global__ void __launch_bounds__(256)
k4_av()
{
    __shared__ __align__(16) float As[16][130];
    __shared__ __align__(16) float Bs[16][64];

    const int tid = threadIdx.x;
    const int batch = blockIdx.y;       // 0..255 = b*16+l
    const int rowTile = blockIdx.x;     // 0..3
    const float* Aa = g_A + (size_t)batch * 512 * 512 + (size_t)rowTile * 128 * 512;
    const float* Vv = g_V + (size_t)batch * 512 * 64;

    const int ti = tid >> 4, tj = tid & 15;
    const int i0 = ti * 8, j0 = tj * 4;
    const int akk = tid & 15, arb = tid >> 4;
    const int bkk = tid >> 4, bjc = tid & 15;

    unsigned long long c2[4][4];
#pragma unroll
    for (int p = 0; p < 4; p++)
#pragma unroll
        for (int j = 0; j < 4; j++) c2[p][j] = 0ull;

    for (int k0 = 0; k0 < 512; k0 += 16) {
#pragma unroll
        for (int it = 0; it < 8; it++) {
            int r = arb + 16 * it;
            As[akk][r] = Aa[(size_t)r * 512 + k0 + akk];
        }
        *(float4*)&Bs[bkk][bjc * 4] = *(const float4*)&Vv[(size_t)(k0 + bkk) * 64 + bjc * 4];
        __syncthreads();
#pragma unroll
        for (int kk = 0; kk < 16; kk++) {
            unsigned long long a2[4];
#pragma unroll
            for (int p = 0; p < 4; p++)
                a2[p] = *(const unsigned long long*)&As[kk][i0 + 2 * p];
            float4 bq = *(const float4*)&Bs[kk][j0];
            unsigned long long bb[4] = { pk2(bq.x), pk2(bq.y), pk2(bq.z), pk2(bq.w) };
#pragma unroll
            for (int p = 0; p < 4; p++)
#pragma unroll
                for (int j = 0; j < 4; j++) ffma2(c2[p][j], a2[p], bb[j]);
        }
        __syncthreads();
    }

    const int b = batch >> 4, l = batch & 15;
#pragma unroll
    for (int p = 0; p < 4; p++) {
        float2 rows[4];
#pragma unroll
        for (int j = 0; j < 4; j++) rows[j] = up2(c2[p][j]);
#pragma unroll
        for (int h = 0; h < 2; h++) {
            int n = rowTile * 128 + i0 + 2 * p + h;
            float v[4];
#pragma unroll
            for (int j = 0; j < 4; j++) v[j] = h ? rows[j].y : rows[j].x;
            float* dst = &g_O[(((b * 512 + n) * 16 + l) * 64) + j0];
            *(float4*)dst = make_float4(v[0], v[1], v[2], v[3]);
        }
    }
}

// =============================================================================
// K5: output projection. out(8192x512) = O(8192x1024) @ Wout(1024x512).
// =============================================================================
__global__ void __launch_bounds__(256)
k5_out(const float* __restrict__ Wout, float* __restrict__ out)
{
    __shared__ __align__(16) float As[16][130];
    __shared__ __align__(16) float Bs[16][128];

    const int tid = threadIdx.x;
    const int colTile = blockIdx.x;   // 0..3
    const int rowTile = blockIdx.y;   // 0..63
    const float* Ag = g_O + (size_t)rowTile * 128 * 1024;
    const int colBase = colTile * 128;

    const int ti = tid >> 4, tj = tid & 15;
    const int i0 = ti * 8, j0 = tj * 8;
    const int akk = tid & 15, arb = tid >> 4;

    unsigned long long c2[4][8];
#pragma unroll
    for (int p = 0; p < 4; p++)
#pragma unroll
        for (int j = 0; j < 8; j++) c2[p][j] = 0ull;

    for (int k0 = 0; k0 < 1024; k0 += 16) {
#pragma unroll
        for (int it = 0; it < 8; it++) {
            int r = arb + 16 * it;
            As[akk][r] = Ag[(size_t)r * 1024 + k0 + akk];
        }
#pragma unroll
        for (int it = 0; it < 2; it++) {
            int li = tid + 256 * it;
            int bkk = li >> 5, bjc = li & 31;
            *(float4*)&Bs[bkk][bjc * 4] =
                *(const float4*)&Wout[(size_t)(k0 + bkk) * 512 + colBase + bjc * 4];
        }
        __syncthreads();
#pragma unroll
        for (int kk = 0; kk < 16; kk++) {
            unsigned long long a2[4];
#pragma unroll
            for (int p = 0; p < 4; p++)
                a2[p] = *(const unsigned long long*)&As[kk][i0 + 2 * p];
            float4 b0 = *(const float4*)&Bs[kk][j0];
            float4 b1 = *(const float4*)&Bs[kk][j0 + 4];
            unsigned long long bb[8] = { pk2(b0.x), pk2(b0.y), pk2(b0.z), pk2(b0.w),
                                         pk2(b1.x), pk2(b1.y), pk2(b1.z), pk2(b1.w) };
#pragma unroll
            for (int p = 0; p < 4; p++)
#pragma unroll
                for (int j = 0; j < 8; j++) ffma2(c2[p][j], a2[p], bb[j]);
        }
        __syncthreads();
    }

#pragma unroll
    for (int p = 0; p < 4; p++) {
        float2 rows[8];
#pragma unroll
        for (int j = 0; j < 8; j++) rows[j] = up2(c2[p][j]);
#pragma unroll
        for (int h = 0; h < 2; h++) {
            int r = rowTile * 128 + i0 + 2 * p + h;
            float v[8];
#pragma unroll
            for (int j = 0; j < 8; j++) v[j] = h ? rows[j].y : rows[j].x;
            float* dst = out + (size_t)r * 512 + colBase + j0;
            *(float4*)dst       = make_float4(v[0], v[1], v[2], v[3]);
            *(float4*)(dst + 4) = make_float4(v[4], v[5], v[6], v[7]);
        }
    }
}

// =============================================================================
extern "C" void kernel_launch(void* const* d_in, const int* in_sizes, int n_in,
                              void* d_out, int out_size)
{
    (void)in_sizes; (void)n_in; (void)out_size;
    const float* x     = (const float*)d_in[0];
    const float* prior = (const float*)d_in[1];
    const float* eps   = (const float*)d_in[2];
    const float* Wq    = (const float*)d_in[3];
    const float* Wk    = (const float*)d_in[4];
    const float* Wv    = (const float*)d_in[5];
    const float* bv    = (const float*)d_in[6];
    const float* sigma = (const float*)d_in[7];
    const float* Wp1   = (const float*)d_in[8];
    const float* bp1   = (const float*)d_in[9];
    const float* Wp2   = (const float*)d_in[10];
    const float* bp2   = (const float*)d_in[11];
    const float* Wout  = (const float*)d_in[12];
    float* out = (float*)d_out;

    k1_proj  <<<dim3(16, 64),     256>>>(x, Wq, Wk, Wv, bv);
    k2_scores<<<dim3(4, 4, 128),  256>>>();
    k3_mix   <<<8192,             256>>>(eps, prior, sigma, Wp1, bp1, Wp2, bp2);
    k4_av    <<<dim3(4, 256),     256>>>();
    k5_out   <<<dim3(4, 64),      256>>>(Wout, out);
}

// round 13
// speedup vs baseline: 1.5242x; 1.5239x over previous
#include <cuda_runtime.h>
#include <cstdint>

// ---------------- problem constants ----------------
#define B_ 16
#define N_ 512
#define H_ 512
#define G_ 8
#define L_ 16
#define D_ 64
#define SCALE_ 0.04419417382415922f   // 512^-0.5

// ---------------- device scratch (static: no allocs allowed) ----------------
__device__ float g_Q[B_*G_*N_*D_];          // (b,g,n,d)  16 MB
__device__ float g_K[B_*G_*N_*D_];          // (b,g,m,d)  16 MB
__device__ float g_V[B_*L_*N_*D_];          // (b,l,m,d)  32 MB
__device__ float g_S[B_*G_*N_*N_];          // (b,g,n,m) 128 MB
__device__ float g_A[B_*L_*N_*N_];          // (b,l,n,m) 256 MB
__device__ float g_O[B_*N_*L_*D_];          // (b,n,l,d)  32 MB

// ---------------- tf32 helpers --------------------------------------------
__device__ __forceinline__ uint32_t f2tf32(float f) {
    uint32_t u;
    asm("cvt.rna.tf32.f32 %0, %1;" : "=r"(u) : "f"(f));
    return u;
}
__device__ __forceinline__ float tf32f(float f) {
    return __uint_as_float(f2tf32(f));
}

// mma.sync m16n8k8 tf32: D += A*B  (A row-major 16x8, B col-major 8x8)
__device__ __forceinline__ void mma8(float* c, const uint32_t* a,
                                     uint32_t b0, uint32_t b1) {
    asm volatile(
        "mma.sync.aligned.m16n8k8.row.col.f32.tf32.tf32.f32 "
        "{%0,%1,%2,%3}, {%4,%5,%6,%7}, {%8,%9}, {%0,%1,%2,%3};"
        : "+f"(c[0]), "+f"(c[1]), "+f"(c[2]), "+f"(c[3])
        : "r"(a[0]), "r"(a[1]), "r"(a[2]), "r"(a[3]), "r"(b0), "r"(b1));
}

// ---------------- shared-tile GEMM machinery -------------------------------
// CTA tile 128(M) x 64(N) x 32(K). 256 threads = 8 warps, 4(M) x 2(N).
// Warp tile 32x32: 2 m-frags (m16) x 4 n-frags (n8), k8 steps.
// sA [128][36] m-major, sB [64][36] n-major — pad 36: (4*row+col)%32 unique
// over fragment lanes -> conflict-free LDS.32.
struct TileSmem { float sA[128 * 36]; float sB[64 * 36]; };

// A: 128 rows x 32 k from gmem row-major (ld floats), pre-offset to k0.
__device__ __forceinline__ void load_a128(float* sA, const float* __restrict__ g,
                                          int ld, int tid) {
#pragma unroll
    for (int it = 0; it < 4; ++it) {
        int f = tid + 256 * it;
        int row = f >> 3, cq = f & 7;
        float4 v = *(const float4*)(g + (size_t)row * ld + cq * 4);
        float* d = sA + row * 36 + cq * 4;
        *(float4*)d = make_float4(tf32f(v.x), tf32f(v.y), tf32f(v.z), tf32f(v.w));
    }
}
// B from [K,N] row-major source (weights / V): transpose into sB[n][k].
__device__ __forceinline__ void load_b_trans(float* sB, const float* __restrict__ g,
                                             int ld, int tid) {
#pragma unroll
    for (int it = 0; it < 8; ++it) {
        int e = tid + 256 * it;
        int k = e >> 6, n = e & 63;
        sB[n * 36 + k] = tf32f(g[(size_t)k * ld + n]);
    }
}
// B from [N,K]-style source (K matrix: 64 tokens x 64 d, take 32-k slice): copy.
__device__ __forceinline__ void load_b_copy64(float* sB, const float* __restrict__ g,
                                              int tid) {
#pragma unroll
    for (int it = 0; it < 2; ++it) {
        int f = tid + 256 * it;
        int n = f >> 3, kq = f & 7;
        float4 v = *(const float4*)(g + (size_t)n * 64 + kq * 4);
        float* d = sB + n * 36 + kq * 4;
        *(float4*)d = make_float4(tf32f(v.x), tf32f(v.y), tf32f(v.z), tf32f(v.w));
    }
}

// One k32 chunk of MMAs. aBase/bBase are per-thread fragment base offsets.
__device__ __forceinline__ void mma_chunk(const float* sA, const float* sB,
                                          float acc[2][4][4], int aBase, int bBase) {
#pragma unroll
    for (int ks = 0; ks < 4; ++ks) {
        uint32_t A[2][4];
#pragma unroll
        for (int mi = 0; mi < 2; ++mi) {
            int ia = aBase + mi * 576 + ks * 8;          // mi*16 rows * 36
            A[mi][0] = __float_as_uint(sA[ia]);          // (g,   t)
            A[mi][1] = __float_as_uint(sA[ia + 288]);    // (g+8, t)
            A[mi][2] = __float_as_uint(sA[ia + 4]);      // (g,   t+4)
            A[mi][3] = __float_as_uint(sA[ia + 292]);    // (g+8, t+4)
        }
#pragma unroll
        for (int ni = 0; ni < 4; ++ni) {
            int ib = bBase + ni * 288 + ks * 8;          // ni*8 rows * 36
            uint32_t b0 = __float_as_uint(sB[ib]);       // (t,   n=g)
            uint32_t b1 = __float_as_uint(sB[ib + 4]);   // (t+4, n=g)
#pragma unroll
            for (int mi = 0; mi < 2; ++mi)
                mma8(acc[mi][ni], A[mi], b0, b1);
        }
    }
}

#define GEMM_SETUP()                                                        \
    __shared__ TileSmem st;                                                 \
    const int tid = threadIdx.x;                                            \
    const int lane = tid & 31, wid = tid >> 5;                              \
    const int gID = lane >> 2, tg = lane & 3;                               \
    const int warpM = wid & 3, warpN = wid >> 2;                            \
    const int aBase = (warpM * 32 + gID) * 36 + tg;                         \
    const int bBase = (warpN * 32 + gID) * 36 + tg;                         \
    float acc[2][4][4];                                                     \
    _Pragma("unroll") for (int mi = 0; mi < 2; ++mi)                        \
    _Pragma("unroll") for (int ni = 0; ni < 4; ++ni)                        \
    _Pragma("unroll") for (int q = 0; q < 4; ++q) acc[mi][ni][q] = 0.f;

// =============================================================================
// K1: QKV projection. C(8192x2048)=X(8192x512)@[Wq|Wk|Wv], scatter + bias.
// grid (32 colTiles of 64, 64 rowTiles of 128)
// =============================================================================
__global__ void __launch_bounds__(256, 3)
tk1(const float* __restrict__ x,  const float* __restrict__ Wq,
    const float* __restrict__ Wk, const float* __restrict__ Wv,
    const float* __restrict__ bv)
{
    GEMM_SETUP();
    const int colTile = blockIdx.x;   // 0..31
    const int rowTile = blockIdx.y;   // 0..63

    const float* Wsrc; int ldB, nBase;
    if (colTile < 8)       { Wsrc = Wq; nBase = colTile * 64;        ldB = 512;  }
    else if (colTile < 16) { Wsrc = Wk; nBase = (colTile - 8) * 64;  ldB = 512;  }
    else                   { Wsrc = Wv; nBase = (colTile - 16) * 64; ldB = 1024; }

    const float* Ag = x + (size_t)rowTile * 128 * 512;

    for (int c = 0; c < 16; ++c) {   // K = 512
        load_a128(st.sA, Ag + c * 32, 512, tid);
        load_b_trans(st.sB, Wsrc + (size_t)(c * 32) * ldB + nBase, ldB, tid);
        __syncthreads();
        mma_chunk(st.sA, st.sB, acc, aBase, bBase);
        __syncthreads();
    }

#pragma unroll
    for (int mi = 0; mi < 2; ++mi)
#pragma unroll
    for (int hf = 0; hf < 2; ++hf) {
        int r = rowTile * 128 + warpM * 32 + mi * 16 + gID + hf * 8;
        int b = r >> 9, n = r & 511;
#pragma unroll
        for (int ni = 0; ni < 4; ++ni) {
            int col = warpN * 32 + ni * 8 + 2 * tg;
            float2 v = make_float2(acc[mi][ni][hf * 2], acc[mi][ni][hf * 2 + 1]);
            if (colTile < 8) {
                float* dst = &g_Q[(((size_t)(b * 8 + colTile) * 512 + n)) * 64 + col];
                *(float2*)dst = v;
            } else if (colTile < 16) {
                float* dst = &g_K[(((size_t)(b * 8 + colTile - 8) * 512 + n)) * 64 + col];
                *(float2*)dst = v;
            } else {
                float2 bb = *(const float2*)(bv + nBase + col);
                v.x += bb.x; v.y += bb.y;
                float* dst = &g_V[(((size_t)(b * 16 + colTile - 16) * 512 + n)) * 64 + col];
                *(float2*)dst = v;
            }
        }
    }
}

// =============================================================================
// K2: scores. per z=(b,g): S(512x512)=Q(512x64)@K(512x64)^T.
// grid (8 colTiles of 64, 4 rowTiles of 128, 128 z)
// =============================================================================
__global__ void __launch_bounds__(256, 3)
tk2()
{
    GEMM_SETUP();
    const int colTile = blockIdx.x;   // 0..7
    const int rowTile = blockIdx.y;   // 0..3
    const int z = blockIdx.z;         // 0..127

    const float* Qg = g_Q + (size_t)z * 512 * 64 + (size_t)rowTile * 128 * 64;
    const float* Kg = g_K + (size_t)z * 512 * 64 + (size_t)colTile * 64 * 64;

    for (int c = 0; c < 2; ++c) {     // K = 64
        load_a128(st.sA, Qg + c * 32, 64, tid);
        load_b_copy64(st.sB, Kg + c * 32, tid);
        __syncthreads();
        mma_chunk(st.sA, st.sB, acc, aBase, bBase);
        __syncthreads();
    }

    float* Sb = g_S + (size_t)z * 512 * 512;
#pragma unroll
    for (int mi = 0; mi < 2; ++mi)
#pragma unroll
    for (int hf = 0; hf < 2; ++hf) {
        int n = rowTile * 128 + warpM * 32 + mi * 16 + gID + hf * 8;
#pragma unroll
        for (int ni = 0; ni < 4; ++ni) {
            int col = colTile * 64 + warpN * 32 + ni * 8 + 2 * tg;
            *(float2*)(Sb + (size_t)n * 512 + col) =
                make_float2(acc[mi][ni][hf * 2], acc[mi][ni][hf * 2 + 1]);
        }
    }
}

// =============================================================================
// K4: AV. per batch=(b,l): O(512x64)=A(512x512)@V(512x64). grid (4, 256)
// =============================================================================
__global__ void __launch_bounds__(256, 3)
tk4()
{
    GEMM_SETUP();
    const int rowTile = blockIdx.x;   // 0..3
    const int batch   = blockIdx.y;   // 0..255 = b*16 + l

    const float* Aa = g_A + (size_t)batch * 512 * 512 + (size_t)rowTile * 128 * 512;
    const float* Vv = g_V + (size_t)batch * 512 * 64;

    for (int c = 0; c < 16; ++c) {    // K = 512
        load_a128(st.sA, Aa + c * 32, 512, tid);
        load_b_trans(st.sB, Vv + (size_t)(c * 32) * 64, 64, tid);
        __syncthreads();
        mma_chunk(st.sA, st.sB, acc, aBase, bBase);
        __syncthreads();
    }

    const int b = batch >> 4, l = batch & 15;
#pragma unroll
    for (int mi = 0; mi < 2; ++mi)
#pragma unroll
    for (int hf = 0; hf < 2; ++hf) {
        int n = rowTile * 128 + warpM * 32 + mi * 16 + gID + hf * 8;
#pragma unroll
        for (int ni = 0; ni < 4; ++ni) {
            int col = warpN * 32 + ni * 8 + 2 * tg;
            float* dst = &g_O[(((size_t)(b * 512 + n) * 16 + l)) * 64 + col];
            *(float2*)dst = make_float2(acc[mi][ni][hf * 2], acc[mi][ni][hf * 2 + 1]);
        }
    }
}

// =============================================================================
// K5: output projection. out(8192x512)=O(8192x1024)@Wout(1024x512).
// grid (8 colTiles of 64, 64 rowTiles of 128)
// =============================================================================
__global__ void __launch_bounds__(256, 3)
tk5(const float* __restrict__ Wout, float* __restrict__ out)
{
    GEMM_SETUP();
    const int colTile = blockIdx.x;   // 0..7
    const int rowTile = blockIdx.y;   // 0..63

    const float* Ag = g_O + (size_t)rowTile * 128 * 1024;

    for (int c = 0; c < 32; ++c) {    // K = 1024
        load_a128(st.sA, Ag + c * 32, 1024, tid);
        load_b_trans(st.sB, Wout + (size_t)(c * 32) * 512 + colTile * 64, 512, tid);
        __syncthreads();
        mma_chunk(st.sA, st.sB, acc, aBase, bBase);
        __syncthreads();
    }

#pragma unroll
    for (int mi = 0; mi < 2; ++mi)
#pragma unroll
    for (int hf = 0; hf < 2; ++hf) {
        int r = rowTile * 128 + warpM * 32 + mi * 16 + gID + hf * 8;
#pragma unroll
        for (int ni = 0; ni < 4; ++ni) {
            int col = colTile * 64 + warpN * 32 + ni * 8 + 2 * tg;
            *(float2*)(out + (size_t)r * 512 + col) =
                make_float2(acc[mi][ni][hf * 2], acc[mi][ni][hf * 2 + 1]);
        }
    }
}

// =============================================================================
// K3 (unchanged, proven): pointwise head-mix + softmax over l.
// =============================================================================
__device__ __forceinline__ float mishf(float x) {
    float t = __expf(fminf(x, 15.f));
    float u = t * t + 2.f * t;
    return x * __fdividef(u, u + 2.f);
}

__global__ void __launch_bounds__(256)
k3_mix(const float* __restrict__ eps,  const float* __restrict__ prior,
       const float* __restrict__ sigma, const float* __restrict__ Wp1,
       const float* __restrict__ bp1,   const float* __restrict__ Wp2,
       const float* __restrict__ bp2)
{
    __shared__ float W1s[128];
    __shared__ float W2s[256];
    __shared__ float b1s[16], b2s[16], sg2[8];

    const int tid = threadIdx.x;
    if (tid < 128) W1s[tid] = Wp1[tid];
    W2s[tid] = Wp2[tid];
    if (tid < 16) { b1s[tid] = bp1[tid]; b2s[tid] = bp2[tid]; }
    if (tid < 8)  { float s = sigma[tid]; sg2[tid] = s * s; }
    __syncthreads();

    const int gidx = blockIdx.x * 256 + tid;
    const int m = gidx & 255;
    const int n = (gidx >> 8) & 511;
    const int b = gidx >> 17;

    const size_t p0 = ((size_t)(b * 512 + n)) * 512 + m;

    float t0[8], t1[8];
    {
        float e0[8], e1[8];
        const float4* ep0 = (const float4*)(eps + p0 * 8);
        const float4* ep1 = (const float4*)(eps + (p0 + 256) * 8);
        *(float4*)&e0[0] = ep0[0]; *(float4*)&e0[4] = ep0[1];
        *(float4*)&e1[0] = ep1[0]; *(float4*)&e1[4] = ep1[1];
#pragma unroll
        for (int g = 0; g < 8; g++) {
            size_t si = ((size_t)(b * 8 + g) * 512 + n) * 512 + m;
            t0[g] = g_S[si]       + sg2[g] * e0[g];
            t1[g] = g_S[si + 256] + sg2[g] * e1[g];
        }
    }

    float h0[16], h1[16];
#pragma unroll
    for (int l = 0; l < 16; l++) {
        float a0 = b1s[l], a1 = b1s[l];
#pragma unroll
        for (int g = 0; g < 8; g++) {
            float w = W1s[g * 16 + l];
            a0 += t0[g] * w; a1 += t1[g] * w;
        }
        h0[l] = mishf(a0); h1[l] = mishf(a1);
    }

    float a0[16], a1[16];
    const size_t pr = ((size_t)(b * 16) * 512 + n) * 512 + m;
    float mx0 = -1e30f, mx1 = -1e30f;
#pragma unroll
    for (int l = 0; l < 16; l++) {
        float s0 = b2s[l], s1 = b2s[l];
#pragma unroll
        for (int j = 0; j < 16; j++) {
            float w = W2s[j * 16 + l];
            s0 += h0[j] * w; s1 += h1[j] * w;
        }
        size_t pl = pr + (size_t)l * (512 * 512);
        s0 = s0 * SCALE_ + prior[pl];
        s1 = s1 * SCALE_ + prior[pl + 256];
        a0[l] = s0; a1[l] = s1;
        mx0 = fmaxf(mx0, s0); mx1 = fmaxf(mx1, s1);
    }

    float sum0 = 0.f, sum1 = 0.f;
#pragma unroll
    for (int l = 0; l < 16; l++) {
        a0[l] = __expf(a0[l] - mx0); sum0 += a0[l];
        a1[l] = __expf(a1[l] - mx1); sum1 += a1[l];
    }
    float r0 = __fdividef(1.f, sum0), r1 = __fdividef(1.f, sum1);
#pragma unroll
    for (int l = 0; l < 16; l++) {
        size_t pl = pr + (size_t)l * (512 * 512);
        g_A[pl]       = a0[l] * r0;
        g_A[pl + 256] = a1[l] * r1;
    }
}

// =============================================================================
extern "C" void kernel_launch(void* const* d_in, const int* in_sizes, int n_in,
                              void* d_out, int out_size)
{
    (void)in_sizes; (void)n_in; (void)out_size;
    const float* x     = (const float*)d_in[0];
    const float* prior = (const float*)d_in[1];
    const float* eps   = (const float*)d_in[2];
    const float* Wq    = (const float*)d_in[3];
    const float* Wk    = (const float*)d_in[4];
    const float* Wv    = (const float*)d_in[5];
    const float* bv    = (const float*)d_in[6];
    const float* sigma = (const float*)d_in[7];
    const float* Wp1   = (const float*)d_in[8];
    const float* bp1   = (const float*)d_in[9];
    const float* Wp2   = (const float*)d_in[10];
    const float* bp2   = (const float*)d_in[11];
    const float* Wout  = (const float*)d_in[12];
    float* out = (float*)d_out;

    tk1   <<<dim3(32, 64),    256>>>(x, Wq, Wk, Wv, bv);
    tk2   <<<dim3(8, 4, 128), 256>>>();
    k3_mix<<<8192,            256>>>(eps, prior, sigma, Wp1, bp1, Wp2, bp2);
    tk4   <<<dim3(4, 256),    256>>>();
    tk5   <<<dim3(8, 64),     256>>>(Wout, out);
}

// round 14
// speedup vs baseline: 1.9193x; 1.2592x over previous
#include <cuda_runtime.h>
#include <cstdint>

// ---------------- problem constants ----------------
#define B_ 16
#define N_ 512
#define H_ 512
#define G_ 8
#define L_ 16
#define D_ 64
#define SCALE_ 0.04419417382415922f   // 512^-0.5

// ---------------- device scratch (static: no allocs allowed) ----------------
__device__ float g_X [B_*N_*H_];            // tf32-rounded x           16 MB
__device__ float g_Wt[2048*512];            // [Wq|Wk|Wv]^T rounded      4 MB
__device__ float g_WOt[512*1024];           // Wout^T rounded            2 MB
__device__ float g_Q [B_*G_*N_*D_];         // (b,g,n,d) tf32           16 MB
__device__ float g_K [B_*G_*N_*D_];         // (b,g,m,d) tf32           16 MB
__device__ float g_Vt[B_*L_*D_*N_];         // (b,l,d,m) tf32 (transposed) 32 MB
__device__ float g_S [B_*G_*N_*N_];         // (b,g,n,m) fp32          128 MB
__device__ float g_A [B_*L_*N_*N_];         // (b,l,n,m) tf32          256 MB
__device__ float g_O [B_*N_*L_*D_];         // (b,n,l,d) tf32           32 MB

// ---------------- tf32 helpers --------------------------------------------
__device__ __forceinline__ uint32_t f2tf32(float f) {
    uint32_t u;
    asm("cvt.rna.tf32.f32 %0, %1;" : "=r"(u) : "f"(f));
    return u;
}
__device__ __forceinline__ float tf32f(float f) {
    return __uint_as_float(f2tf32(f));
}

// mma.sync m16n8k8 tf32: D += A*B  (A row-major 16x8, B col-major 8x8)
__device__ __forceinline__ void mma8(float* c, const uint32_t* a,
                                     uint32_t b0, uint32_t b1) {
    asm volatile(
        "mma.sync.aligned.m16n8k8.row.col.f32.tf32.tf32.f32 "
        "{%0,%1,%2,%3}, {%4,%5,%6,%7}, {%8,%9}, {%0,%1,%2,%3};"
        : "+f"(c[0]), "+f"(c[1]), "+f"(c[2]), "+f"(c[3])
        : "r"(a[0]), "r"(a[1]), "r"(a[2]), "r"(a[3]), "r"(b0), "r"(b1));
}

// ---------------- cp.async helpers ----------------------------------------
__device__ __forceinline__ uint32_t smem_u32(const void* p) {
    uint32_t a;
    asm("{ .reg .u64 t; cvta.to.shared.u64 t, %1; cvt.u32.u64 %0, t; }" : "=r"(a) : "l"(p));
    return a;
}
__device__ __forceinline__ void cpa16(uint32_t dst, const float* src) {
    asm volatile("cp.async.cg.shared.global [%0], [%1], 16;" :: "r"(dst), "l"(src));
}
#define CPA_COMMIT() asm volatile("cp.async.commit_group;" ::: "memory")
#define CPA_WAIT1()  asm volatile("cp.async.wait_group 1;" ::: "memory")
#define CPA_WAIT0()  asm volatile("cp.async.wait_group 0;" ::: "memory")

// ---------------- shared-tile GEMM machinery -------------------------------
// CTA tile 128(M) x 64(N) x 32(K). 256 threads = 8 warps, 4(M) x 2(N).
// Warp tile 32x32: 2 m-frags (m16) x 4 n-frags (n8), k8 steps.
// sA [128][36] m-major, sB [64][36] n-major. Pad 36 -> conflict-free frag LDS;
// 36 floats = 144 B = 9*16 B so every cp.async dst stays 16B-aligned.
#define STAGE_FLOATS (128*36 + 64*36)   // 6912 floats = 27648 B
#define STAGE_BYTES  (STAGE_FLOATS * 4)
#define NSTAGE 3
#define DSMEM_BYTES (NSTAGE * STAGE_BYTES)   // 82944 B

// issue A tile: 128 rows x 32 k, row-major gmem (ld floats), src pre-offset to k0
__device__ __forceinline__ void cpa_a128(uint32_t sA, const float* __restrict__ g,
                                         int ld, int tid) {
#pragma unroll
    for (int it = 0; it < 4; ++it) {
        int f = tid + 256 * it;
        int row = f >> 3, kq = f & 7;
        cpa16(sA + (uint32_t)(row * 144 + kq * 16), g + (size_t)row * ld + kq * 4);
    }
}
// issue B tile: 64 rows x 32 k, row-major gmem
__device__ __forceinline__ void cpa_b64(uint32_t sB, const float* __restrict__ g,
                                        int ld, int tid) {
#pragma unroll
    for (int it = 0; it < 2; ++it) {
        int f = tid + 256 * it;
        int row = f >> 3, kq = f & 7;
        cpa16(sB + (uint32_t)(row * 144 + kq * 16), g + (size_t)row * ld + kq * 4);
    }
}

// One k32 chunk of MMAs (layout identical to R13 — proven).
__device__ __forceinline__ void mma_chunk(const float* sA, const float* sB,
                                          float acc[2][4][4], int aBase, int bBase) {
#pragma unroll
    for (int ks = 0; ks < 4; ++ks) {
        uint32_t A[2][4];
#pragma unroll
        for (int mi = 0; mi < 2; ++mi) {
            int ia = aBase + mi * 576 + ks * 8;          // mi*16 rows * 36
            A[mi][0] = __float_as_uint(sA[ia]);
            A[mi][1] = __float_as_uint(sA[ia + 288]);
            A[mi][2] = __float_as_uint(sA[ia + 4]);
            A[mi][3] = __float_as_uint(sA[ia + 292]);
        }
#pragma unroll
        for (int ni = 0; ni < 4; ++ni) {
            int ib = bBase + ni * 288 + ks * 8;          // ni*8 rows * 36
            uint32_t b0 = __float_as_uint(sB[ib]);
            uint32_t b1 = __float_as_uint(sB[ib + 4]);
#pragma unroll
            for (int mi = 0; mi < 2; ++mi)
                mma8(acc[mi][ni], A[mi], b0, b1);
        }
    }
}

#define GEMM_SETUP()                                                        \
    extern __shared__ float dyn[];                                          \
    const int tid = threadIdx.x;                                            \
    const int lane = tid & 31, wid = tid >> 5;                              \
    const int gID = lane >> 2, tg = lane & 3;                               \
    const int warpM = wid & 3, warpN = wid >> 2;                            \
    const int aBase = (warpM * 32 + gID) * 36 + tg;                         \
    const int bBase = (warpN * 32 + gID) * 36 + tg;                         \
    const uint32_t smem0 = smem_u32(dyn);                                   \
    float acc[2][4][4];                                                     \
    _Pragma("unroll") for (int mi = 0; mi < 2; ++mi)                        \
    _Pragma("unroll") for (int ni = 0; ni < 4; ++ni)                        \
    _Pragma("unroll") for (int q = 0; q < 4; ++q) acc[mi][ni][q] = 0.f;

// pipeline: ISSUE(c, stage_u32_base) is a statement issuing both tiles of chunk c
#define GEMM_PIPELINE(C, ISSUE)                                             \
    { ISSUE(0, smem0); CPA_COMMIT();                                        \
      ISSUE(1, smem0 + STAGE_BYTES); CPA_COMMIT(); }                        \
    for (int c = 0; c < (C); ++c) {                                         \
        if (c + 1 < (C)) { CPA_WAIT1(); } else { CPA_WAIT0(); }             \
        __syncthreads();                                                    \
        if (c + 2 < (C)) {                                                  \
            uint32_t sb = smem0 + ((c + 2) % NSTAGE) * STAGE_BYTES;         \
            ISSUE(c + 2, sb); CPA_COMMIT();                                 \
        }                                                                   \
        const float* sA = dyn + (c % NSTAGE) * STAGE_FLOATS;                \
        mma_chunk(sA, sA + 128 * 36, acc, aBase, bBase);                    \
    }

// =============================================================================
// prep: round x -> g_X; build g_Wt = [Wq|Wk|Wv]^T rounded; g_WOt = Wout^T rounded
// =============================================================================
__global__ void __launch_bounds__(256)
prep(const float* __restrict__ x,  const float* __restrict__ Wq,
     const float* __restrict__ Wk, const float* __restrict__ Wv,
     const float* __restrict__ Wout)
{
    int i = blockIdx.x * 256 + threadIdx.x;
    const int NX = B_*N_*H_;           // 4194304
    const int NW = 2048 * 512;         // 1048576
    const int NO = 512 * 1024;         // 524288
    if (i < NX) {
        g_X[i] = tf32f(x[i]);
    } else if (i < NX + NW) {
        int j = i - NX;
        int c = j >> 9, h = j & 511;
        float v;
        if (c < 512)        v = Wq[(size_t)h * 512 + c];
        else if (c < 1024)  v = Wk[(size_t)h * 512 + (c - 512)];
        else                v = Wv[(size_t)h * 1024 + (c - 1024)];
        g_Wt[j] = tf32f(v);
    } else if (i < NX + NW + NO) {
        int j = i - NX - NW;
        int c = j >> 10, k = j & 1023;
        g_WOt[j] = tf32f(Wout[(size_t)k * 512 + c]);
    }
}

// =============================================================================
// K1: QKV projection. C(8192x2048)=g_X(8192x512)@g_Wt^T, scatter + bias.
// grid (32 colTiles of 64, 64 rowTiles of 128). Q/K rounded; V written
// TRANSPOSED+rounded into g_Vt (b,l,d,m).
// =============================================================================
__global__ void __launch_bounds__(256)
tk1(const float* __restrict__ bv)
{
    GEMM_SETUP();
    const int colTile = blockIdx.x;   // 0..31
    const int rowTile = blockIdx.y;   // 0..63

    const float* Ag = g_X + (size_t)rowTile * 128 * 512;
    const float* Bg = g_Wt + (size_t)colTile * 64 * 512;

#define K1_ISSUE(c, sb) \
    { cpa_a128((sb), Ag + (c) * 32, 512, tid); \
      cpa_b64((sb) + 128 * 144, Bg + (c) * 32, 512, tid); }
    GEMM_PIPELINE(16, K1_ISSUE);
#undef K1_ISSUE

#pragma unroll
    for (int mi = 0; mi < 2; ++mi)
#pragma unroll
    for (int hf = 0; hf < 2; ++hf) {
        int r = rowTile * 128 + warpM * 32 + mi * 16 + gID + hf * 8;
        int b = r >> 9, n = r & 511;
#pragma unroll
        for (int ni = 0; ni < 4; ++ni) {
            int col = warpN * 32 + ni * 8 + 2 * tg;   // 0..63 within tile
            float vx = acc[mi][ni][hf * 2], vy = acc[mi][ni][hf * 2 + 1];
            if (colTile < 8) {
                int g = colTile;
                float* dst = &g_Q[(((size_t)(b * 8 + g) * 512 + n)) * 64 + col];
                *(float2*)dst = make_float2(tf32f(vx), tf32f(vy));
            } else if (colTile < 16) {
                int g = colTile - 8;
                float* dst = &g_K[(((size_t)(b * 8 + g) * 512 + n)) * 64 + col];
                *(float2*)dst = make_float2(tf32f(vx), tf32f(vy));
            } else {
                int l = colTile - 16;
                float2 bb = *(const float2*)(bv + l * 64 + col);
                float* base = &g_Vt[(((size_t)(b * 16 + l) * 64 + col)) * 512 + n];
                base[0]   = tf32f(vx + bb.x);     // (d=col,   m=n)
                base[512] = tf32f(vy + bb.y);     // (d=col+1, m=n)
            }
        }
    }
}

// =============================================================================
// K2: scores. per z=(b,g): S(512x512)=Q(512x64)@K(512x64)^T. fp32 S out.
// grid (8 colTiles of 64, 4 rowTiles of 128, 128 z)
// =============================================================================
__global__ void __launch_bounds__(256)
tk2()
{
    GEMM_SETUP();
    const int colTile = blockIdx.x;   // 0..7
    const int rowTile = blockIdx.y;   // 0..3
    const int z = blockIdx.z;         // 0..127

    const float* Qg = g_Q + (size_t)z * 512 * 64 + (size_t)rowTile * 128 * 64;
    const float* Kg = g_K + (size_t)z * 512 * 64 + (size_t)colTile * 64 * 64;

#define K2_ISSUE(c, sb) \
    { cpa_a128((sb), Qg + (c) * 32, 64, tid); \
      cpa_b64((sb) + 128 * 144, Kg + (c) * 32, 64, tid); }
    GEMM_PIPELINE(2, K2_ISSUE);
#undef K2_ISSUE

    float* Sb = g_S + (size_t)z * 512 * 512;
#pragma unroll
    for (int mi = 0; mi < 2; ++mi)
#pragma unroll
    for (int hf = 0; hf < 2; ++hf) {
        int n = rowTile * 128 + warpM * 32 + mi * 16 + gID + hf * 8;
#pragma unroll
        for (int ni = 0; ni < 4; ++ni) {
            int col = colTile * 64 + warpN * 32 + ni * 8 + 2 * tg;
            *(float2*)(Sb + (size_t)n * 512 + col) =
                make_float2(acc[mi][ni][hf * 2], acc[mi][ni][hf * 2 + 1]);
        }
    }
}

// =============================================================================
// K4: AV. per batch=(b,l): O(512x64)=A(512x512)@Vt^T. grid (4, 256).
// O written rounded (tk5 operand).
// =============================================================================
__global__ void __launch_bounds__(256)
tk4()
{
    GEMM_SETUP();
    const int rowTile = blockIdx.x;   // 0..3
    const int batch   = blockIdx.y;   // 0..255 = b*16 + l

    const float* Aa = g_A + (size_t)batch * 512 * 512 + (size_t)rowTile * 128 * 512;
    const float* Bg = g_Vt + (size_t)batch * 64 * 512;   // rows d (64), ld 512 over m

#define K4_ISSUE(c, sb) \
    { cpa_a128((sb), Aa + (c) * 32, 512, tid); \
      cpa_b64((sb) + 128 * 144, Bg + (c) * 32, 512, tid); }
    GEMM_PIPELINE(16, K4_ISSUE);
#undef K4_ISSUE

    const int b = batch >> 4, l = batch & 15;
#pragma unroll
    for (int mi = 0; mi < 2; ++mi)
#pragma unroll
    for (int hf = 0; hf < 2; ++hf) {
        int n = rowTile * 128 + warpM * 32 + mi * 16 + gID + hf * 8;
#pragma unroll
        for (int ni = 0; ni < 4; ++ni) {
            int col = warpN * 32 + ni * 8 + 2 * tg;
            float* dst = &g_O[(((size_t)(b * 512 + n) * 16 + l)) * 64 + col];
            *(float2*)dst = make_float2(tf32f(acc[mi][ni][hf * 2]),
                                        tf32f(acc[mi][ni][hf * 2 + 1]));
        }
    }
}

// =============================================================================
// K5: output projection. out(8192x512)=g_O(8192x1024)@g_WOt^T.
// grid (8 colTiles of 64, 64 rowTiles of 128)
// =============================================================================
__global__ void __launch_bounds__(256)
tk5(float* __restrict__ out)
{
    GEMM_SETUP();
    const int colTile = blockIdx.x;   // 0..7
    const int rowTile = blockIdx.y;   // 0..63

    const float* Ag = g_O + (size_t)rowTile * 128 * 1024;
    const float* Bg = g_WOt + (size_t)colTile * 64 * 1024;

#define K5_ISSUE(c, sb) \
    { cpa_a128((sb), Ag + (c) * 32, 1024, tid); \
      cpa_b64((sb) + 128 * 144, Bg + (c) * 32, 1024, tid); }
    GEMM_PIPELINE(32, K5_ISSUE);
#undef K5_ISSUE

#pragma unroll
    for (int mi = 0; mi < 2; ++mi)
#pragma unroll
    for (int hf = 0; hf < 2; ++hf) {
        int r = rowTile * 128 + warpM * 32 + mi * 16 + gID + hf * 8;
#pragma unroll
        for (int ni = 0; ni < 4; ++ni) {
            int col = colTile * 64 + warpN * 32 + ni * 8 + 2 * tg;
            *(float2*)(out + (size_t)r * 512 + col) =
                make_float2(acc[mi][ni][hf * 2], acc[mi][ni][hf * 2 + 1]);
        }
    }
}

// =============================================================================
// K3: pointwise head-mix + softmax over l. (Unchanged except g_A stores are
// tf32-rounded — tk4 would have rounded them anyway.)
// =============================================================================
__device__ __forceinline__ float mishf(float x) {
    float t = __expf(fminf(x, 15.f));
    float u = t * t + 2.f * t;
    return x * __fdividef(u, u + 2.f);
}

__global__ void __launch_bounds__(256)
k3_mix(const float* __restrict__ eps,  const float* __restrict__ prior,
       const float* __restrict__ sigma, const float* __restrict__ Wp1,
       const float* __restrict__ bp1,   const float* __restrict__ Wp2,
       const float* __restrict__ bp2)
{
    __shared__ float W1s[128];
    __shared__ float W2s[256];
    __shared__ float b1s[16], b2s[16], sg2[8];

    const int tid = threadIdx.x;
    if (tid < 128) W1s[tid] = Wp1[tid];
    W2s[tid] = Wp2[tid];
    if (tid < 16) { b1s[tid] = bp1[tid]; b2s[tid] = bp2[tid]; }
    if (tid < 8)  { float s = sigma[tid]; sg2[tid] = s * s; }
    __syncthreads();

    const int gidx = blockIdx.x * 256 + tid;
    const int m = gidx & 255;
    const int n = (gidx >> 8) & 511;
    const int b = gidx >> 17;

    const size_t p0 = ((size_t)(b * 512 + n)) * 512 + m;

    float t0[8], t1[8];
    {
        float e0[8], e1[8];
        const float4* ep0 = (const float4*)(eps + p0 * 8);
        const float4* ep1 = (const float4*)(eps + (p0 + 256) * 8);
        *(float4*)&e0[0] = ep0[0]; *(float4*)&e0[4] = ep0[1];
        *(float4*)&e1[0] = ep1[0]; *(float4*)&e1[4] = ep1[1];
#pragma unroll
        for (int g = 0; g < 8; g++) {
            size_t si = ((size_t)(b * 8 + g) * 512 + n) * 512 + m;
            t0[g] = g_S[si]       + sg2[g] * e0[g];
            t1[g] = g_S[si + 256] + sg2[g] * e1[g];
        }
    }

    float h0[16], h1[16];
#pragma unroll
    for (int l = 0; l < 16; l++) {
        float a0 = b1s[l], a1 = b1s[l];
#pragma unroll
        for (int g = 0; g < 8; g++) {
            float w = W1s[g * 16 + l];
            a0 += t0[g] * w; a1 += t1[g] * w;
        }
        h0[l] = mishf(a0); h1[l] = mishf(a1);
    }

    float a0[16], a1[16];
    const size_t pr = ((size_t)(b * 16) * 512 + n) * 512 + m;
    float mx0 = -1e30f, mx1 = -1e30f;
#pragma unroll
    for (int l = 0; l < 16; l++) {
        float s0 = b2s[l], s1 = b2s[l];
#pragma unroll
        for (int j = 0; j < 16; j++) {
            float w = W2s[j * 16 + l];
            s0 += h0[j] * w; s1 += h1[j] * w;
        }
        size_t pl = pr + (size_t)l * (512 * 512);
        s0 = s0 * SCALE_ + prior[pl];
        s1 = s1 * SCALE_ + prior[pl + 256];
        a0[l] = s0; a1[l] = s1;
        mx0 = fmaxf(mx0, s0); mx1 = fmaxf(mx1, s1);
    }

    float sum0 = 0.f, sum1 = 0.f;
#pragma unroll
    for (int l = 0; l < 16; l++) {
        a0[l] = __expf(a0[l] - mx0); sum0 += a0[l];
        a1[l] = __expf(a1[l] - mx1); sum1 += a1[l];
    }
    float r0 = __fdividef(1.f, sum0), r1 = __fdividef(1.f, sum1);
#pragma unroll
    for (int l = 0; l < 16; l++) {
        size_t pl = pr + (size_t)l * (512 * 512);
        g_A[pl]       = tf32f(a0[l] * r0);
        g_A[pl + 256] = tf32f(a1[l] * r1);
    }
}

// =============================================================================
extern "C" void kernel_launch(void* const* d_in, const int* in_sizes, int n_in,
                              void* d_out, int out_size)
{
    (void)in_sizes; (void)n_in; (void)out_size;
    const float* x     = (const float*)d_in[0];
    const float* prior = (const float*)d_in[1];
    const float* eps   = (const float*)d_in[2];
    const float* Wq    = (const float*)d_in[3];
    const float* Wk    = (const float*)d_in[4];
    const float* Wv    = (const float*)d_in[5];
    const float* bv    = (const float*)d_in[6];
    const float* sigma = (const float*)d_in[7];
    const float* Wp1   = (const float*)d_in[8];
    const float* bp1   = (const float*)d_in[9];
    const float* Wp2   = (const float*)d_in[10];
    const float* bp2   = (const float*)d_in[11];
    const float* Wout  = (const float*)d_in[12];
    float* out = (float*)d_out;

    cudaFuncSetAttribute(tk1, cudaFuncAttributeMaxDynamicSharedMemorySize, DSMEM_BYTES);
    cudaFuncSetAttribute(tk2, cudaFuncAttributeMaxDynamicSharedMemorySize, DSMEM_BYTES);
    cudaFuncSetAttribute(tk4, cudaFuncAttributeMaxDynamicSharedMemorySize, DSMEM_BYTES);
    cudaFuncSetAttribute(tk5, cudaFuncAttributeMaxDynamicSharedMemorySize, DSMEM_BYTES);

    // prep covers 4194304 + 1048576 + 524288 = 5767168 elements
    prep  <<<22528, 256>>>(x, Wq, Wk, Wv, Wout);
    tk1   <<<dim3(32, 64),    256, DSMEM_BYTES>>>(bv);
    tk2   <<<dim3(8, 4, 128), 256, DSMEM_BYTES>>>();
    k3_mix<<<8192,            256>>>(eps, prior, sigma, Wp1, bp1, Wp2, bp2);
    tk4   <<<dim3(4, 256),    256, DSMEM_BYTES>>>();
    tk5   <<<dim3(8, 64),     256, DSMEM_BYTES>>>(out);
}